// round 15
// baseline (speedup 1.0000x reference)
#include <cuda_runtime.h>

// ---------------------------------------------------------------------------
// SimpleRNN: x[128,1024,256], W_i2h[512,768] (=[Wx|Wh]), b_i2h[512],
//            W_h2o[256,512], b_h2o[256]
// out = concat( outputs[128,1024,256], h_last[128,512] ), fp32
// ---------------------------------------------------------------------------

namespace {
constexpr int B_ = 128;   // batch
constexpr int S_ = 1024;  // seq
constexpr int I_ = 256;   // in
constexpr int H_ = 512;   // hid
constexpr int O_ = 256;   // out
constexpr int BG = 8;     // batch groups (16 b each)
constexpr int BSL = B_ / BG;        // 16 batch rows per group
constexpr int JH = 32;              // j-halves (16 j each)
constexpr int NFLAG = BG * S_ * JH; // per-(bg,t,jh) done flags
}

// Scratch (allocation-free rule: __device__ globals)
__device__ float    g_xw[(size_t)S_ * B_ * H_];   // 256 MB, [t][b][h]
__device__ float    g_hs[(size_t)S_ * B_ * H_];   // 256 MB, [t][b][h]
__device__ unsigned g_flag[NFLAG];

// ---------------------------------------------------------------------------
__global__ void zero_flag_kernel() {
    int i = blockIdx.x * blockDim.x + threadIdx.x;
    if (i < NFLAG) g_flag[i] = 0u;
}

// ---------------------------------------------------------------------------
// C[r][c] = sum_k A'[r][k]*B[c][k] + bias[c].  128x128 tile, 8x8 micro-tile
// (split halves -> conflict-free LDS.128).  Row r: hi=r/D, lo=r%D;
// A row = (lo*SWAP + hi)*K.   [unchanged — verified 69.4% fma]
template<int K, int N, int BSTR, int D, int SWAP>
__global__ void __launch_bounds__(256, 2) gemm_bias_kernel(
    const float* __restrict__ A, const float* __restrict__ Bm,
    const float* __restrict__ bias, float* __restrict__ C)
{
    __shared__ float As[16][132];
    __shared__ float Bs[16][132];
    const int tid = threadIdx.x;
    const int r0  = blockIdx.y * 128;
    const int c0  = blockIdx.x * 128;

    const int arow_l = tid >> 1;
    const int ak     = (tid & 1) * 8;
    const int r  = r0 + arow_l;
    const int hi = r / D, lo = r % D;
    const float* Arow = A + ((size_t)lo * SWAP + hi) * K + ak;
    const float* Brow = Bm + (size_t)(c0 + arow_l) * BSTR + ak;

    const int ty = tid >> 4, tx = tid & 15;
    float acc[2][4][2][4] = {};

    float4 a0 = *reinterpret_cast<const float4*>(Arow);
    float4 a1 = *reinterpret_cast<const float4*>(Arow + 4);
    float4 b0 = *reinterpret_cast<const float4*>(Brow);
    float4 b1 = *reinterpret_cast<const float4*>(Brow + 4);

    for (int kc = 0; kc < K; kc += 16) {
        __syncthreads();
        As[ak+0][arow_l]=a0.x; As[ak+1][arow_l]=a0.y; As[ak+2][arow_l]=a0.z; As[ak+3][arow_l]=a0.w;
        As[ak+4][arow_l]=a1.x; As[ak+5][arow_l]=a1.y; As[ak+6][arow_l]=a1.z; As[ak+7][arow_l]=a1.w;
        Bs[ak+0][arow_l]=b0.x; Bs[ak+1][arow_l]=b0.y; Bs[ak+2][arow_l]=b0.z; Bs[ak+3][arow_l]=b0.w;
        Bs[ak+4][arow_l]=b1.x; Bs[ak+5][arow_l]=b1.y; Bs[ak+6][arow_l]=b1.z; Bs[ak+7][arow_l]=b1.w;
        __syncthreads();
        if (kc + 16 < K) {
            a0 = *reinterpret_cast<const float4*>(Arow + kc + 16);
            a1 = *reinterpret_cast<const float4*>(Arow + kc + 16 + 4);
            b0 = *reinterpret_cast<const float4*>(Brow + kc + 16);
            b1 = *reinterpret_cast<const float4*>(Brow + kc + 16 + 4);
        }
#pragma unroll
        for (int kk = 0; kk < 16; ++kk) {
            float4 af0 = *reinterpret_cast<const float4*>(&As[kk][ty * 4]);
            float4 af1 = *reinterpret_cast<const float4*>(&As[kk][ty * 4 + 64]);
            float4 bf0 = *reinterpret_cast<const float4*>(&Bs[kk][tx * 4]);
            float4 bf1 = *reinterpret_cast<const float4*>(&Bs[kk][tx * 4 + 64]);
            float av[2][4] = {{af0.x,af0.y,af0.z,af0.w},{af1.x,af1.y,af1.z,af1.w}};
            float bv[2][4] = {{bf0.x,bf0.y,bf0.z,bf0.w},{bf1.x,bf1.y,bf1.z,bf1.w}};
#pragma unroll
            for (int ri = 0; ri < 2; ++ri)
#pragma unroll
                for (int i = 0; i < 4; ++i)
#pragma unroll
                    for (int ci = 0; ci < 2; ++ci)
#pragma unroll
                        for (int j = 0; j < 4; ++j)
                            acc[ri][i][ci][j] = fmaf(av[ri][i], bv[ci][j], acc[ri][i][ci][j]);
        }
    }

    float4 bsv0 = *reinterpret_cast<const float4*>(bias + c0 + tx * 4);
    float4 bsv1 = *reinterpret_cast<const float4*>(bias + c0 + 64 + tx * 4);
    float bb[2][4] = {{bsv0.x,bsv0.y,bsv0.z,bsv0.w},{bsv1.x,bsv1.y,bsv1.z,bsv1.w}};
#pragma unroll
    for (int ri = 0; ri < 2; ++ri)
#pragma unroll
        for (int i = 0; i < 4; ++i) {
            const size_t rowoff = (size_t)(r0 + ri * 64 + ty * 4 + i) * N;
#pragma unroll
            for (int ci = 0; ci < 2; ++ci) {
                float4 v;
                v.x = acc[ri][i][ci][0] + bb[ci][0];
                v.y = acc[ri][i][ci][1] + bb[ci][1];
                v.z = acc[ri][i][ci][2] + bb[ci][2];
                v.w = acc[ri][i][ci][3] + bb[ci][3];
                *reinterpret_cast<float4*>(C + rowoff + c0 + ci * 64 + tx * 4) = v;
            }
        }
}

// ---------------------------------------------------------------------------
// Multi-value butterfly: merge HALF*2 accs across lanes at xor-offset O.
#define RED_LEVEL(O, HALF)                                                   \
    {                                                                        \
        const bool up_ = (lane & (O)) != 0;                                  \
        _Pragma("unroll")                                                    \
        for (int q_ = 0; q_ < (HALF); ++q_) {                                \
            float s_ = up_ ? A[q_] : A[q_ + (HALF)];                         \
            float r_ = __shfl_xor_sync(0xffffffffu, s_, (O));                \
            A[q_] = (up_ ? A[q_ + (HALF)] : A[q_]) + r_;                     \
        }                                                                    \
    }

#define TEAM_BAR() asm volatile("bar.sync %0, 128;" :: "r"(barid) : "memory")

// Persistent scan, TWO independent chains per CTA.
// Grid: 128 CTAs; CTA x: jh = x&31 (j in [jh*16, jh*16+16)), g = x>>5.
// Team 0 (warps 0-3): batch group g;  team 1 (warps 4-7): batch group g+4.
// The two chains are independent -> one team's poll/stage latency is hidden
// behind the other team's FMA burst on the shared SMSPs.
// Per warp: 4 j rows; lane owns k-slice {4*lane+128*i}; 64 accs (16b x 4j);
// 62-shuffle merge leaves 2 finished outputs per lane.
__global__ void __launch_bounds__(256, 1) rnn_scan_kernel(const float* __restrict__ W)
{
    const int cta   = blockIdx.x;      // 0..127
    const int jh    = cta & 31;        // j-half
    const int g     = cta >> 5;        // 0..3
    const int tid   = threadIdx.x;
    const int team  = tid >> 7;        // 0 or 1
    const int tt    = tid & 127;       // tid within team
    const int warp  = tt >> 5;         // 0..3 within team
    const int lane  = tid & 31;
    const int bg    = g + team * 4;    // this team's batch group
    const int jbase = jh * 16 + warp * 4;
    const int barid = team + 1;        // named barrier per team

    __shared__ float hsm[2][BSL * H_];   // 2 x 32 KB: h_{t-1} per team
    float* hb = hsm[team];

    // Register-resident Wh slice: w4[jj][i] = Wh[jbase+jj][128*i + 4*lane ..+3]
    float4 w4[4][4];
#pragma unroll
    for (int jj = 0; jj < 4; ++jj)
#pragma unroll
        for (int i = 0; i < 4; ++i)
            w4[jj][i] = *reinterpret_cast<const float4*>(
                W + (size_t)(jbase + jj) * (I_ + H_) + I_ + 128 * i + 4 * lane);

    unsigned* flg = g_flag + (size_t)bg * S_ * JH;   // [t][jh]
    const int ob = lane >> 1;                 // batch row this lane finalizes
    const int oj = jbase + (lane & 1) * 2;    // first of 2 consecutive j's

    for (int t = 0; t < S_; ++t) {
        float s0 = 0.f, s1 = 0.f;
        const size_t rowoff = ((size_t)t * B_ + bg * BSL + ob) * H_ + oj;
        float2 xv;

        if (t > 0) {
            // acquire: warp 0 of the team polls the 32 per-jh flags of t-1
            if (warp == 0) {
                const unsigned* f = flg + (size_t)(t - 1) * JH + lane;
                unsigned v;
                do {
                    asm volatile("ld.relaxed.gpu.global.u32 %0, [%1];"
                                 : "=r"(v) : "l"(f) : "memory");
                } while (!__all_sync(0xffffffffu, v != 0u));
                asm volatile("fence.acq_rel.gpu;" ::: "memory");
            }
            TEAM_BAR();

            xv = *reinterpret_cast<const float2*>(g_xw + rowoff);  // early LDG
            {   // stage h_{t-1} for this bg (32 KB, 16 float4/thread)
                const float4* src = reinterpret_cast<const float4*>(
                    g_hs + ((size_t)(t - 1) * B_ + bg * BSL) * H_);
                float4* dst = reinterpret_cast<float4*>(hb);
#pragma unroll
                for (int i = 0; i < 16; ++i)
                    dst[tt + 128 * i] = src[tt + 128 * i];
            }
            TEAM_BAR();

            float A[64];   // A[b*4+jj]
#pragma unroll
            for (int q = 0; q < 64; ++q) A[q] = 0.f;
#pragma unroll
            for (int i = 0; i < 4; ++i) {
                const int kofs = 4 * lane + 128 * i;
#pragma unroll
                for (int b = 0; b < 16; ++b) {
                    float4 hv = *reinterpret_cast<const float4*>(hb + b * H_ + kofs);
#pragma unroll
                    for (int jj = 0; jj < 4; ++jj) {
                        float a = A[b * 4 + jj];
                        a = fmaf(hv.x, w4[jj][i].x, a);
                        a = fmaf(hv.y, w4[jj][i].y, a);
                        a = fmaf(hv.z, w4[jj][i].z, a);
                        a = fmaf(hv.w, w4[jj][i].w, a);
                        A[b * 4 + jj] = a;
                    }
                }
            }
            RED_LEVEL(16, 32)
            RED_LEVEL(8, 16)
            RED_LEVEL(4, 8)
            RED_LEVEL(2, 4)
            RED_LEVEL(1, 2)
            s0 = A[0];
            s1 = A[1];
        } else {
            xv = *reinterpret_cast<const float2*>(g_xw + rowoff);
        }

        float2 hv2;
        hv2.x = tanhf(xv.x + s0);
        hv2.y = tanhf(xv.y + s1);
        *reinterpret_cast<float2*>(g_hs + rowoff) = hv2;

        TEAM_BAR();
        if (tt == 0) {   // release: publish this team's (bg, jh) slice of h_t
            asm volatile("fence.acq_rel.gpu;" ::: "memory");
            asm volatile("st.relaxed.gpu.global.u32 [%0], %1;"
                         :: "l"(flg + (size_t)t * JH + jh), "r"(1u) : "memory");
        }
    }
}

// ---------------------------------------------------------------------------
__global__ void copy_hlast_kernel(float* __restrict__ out) {
    int i = blockIdx.x * blockDim.x + threadIdx.x;
    out[i] = g_hs[(size_t)(S_ - 1) * B_ * H_ + i];   // [b][h] slice, contiguous
}

// ---------------------------------------------------------------------------
extern "C" void kernel_launch(void* const* d_in, const int* in_sizes, int n_in,
                              void* d_out, int out_size)
{
    const float* x  = (const float*)d_in[0];   // [128,1024,256]
    const float* Wi = (const float*)d_in[1];   // [512,768]
    const float* bi = (const float*)d_in[2];   // [512]
    const float* Wo = (const float*)d_in[3];   // [256,512]
    const float* bo = (const float*)d_in[4];   // [256]
    float* out = (float*)d_out;

    float* xw_d = nullptr;
    float* hs_d = nullptr;
    cudaGetSymbolAddress((void**)&xw_d, g_xw);
    cudaGetSymbolAddress((void**)&hs_d, g_hs);

    // reset sync flags (graph replays must be deterministic)
    zero_flag_kernel<<<(NFLAG + 255) / 256, 256>>>();

    // Phase 1: xW[t][b][h]  (r = t*128+b, A row = (b*S_+t)*I_)
    {
        dim3 g(H_ / 128, (S_ * B_) / 128);
        gemm_bias_kernel<I_, H_, I_ + H_, B_, S_><<<g, 256>>>(x, Wi, bi, xw_d);
    }

    // Phase 2: sequential scan (persistent, 128 co-resident CTAs, 2 chains/CTA)
    rnn_scan_kernel<<<128, 256>>>(Wi);

    // Phase 3: outputs[b][s][o]  (r = b*S_+s, A row = (s*B_+b)*H_)
    {
        dim3 g(O_ / 128, (B_ * S_) / 128);
        gemm_bias_kernel<H_, O_, H_, S_, B_><<<g, 256>>>(hs_d, Wo, bo, out);
    }

    // h_last
    if (out_size >= B_ * S_ * O_ + B_ * H_)
        copy_hlast_kernel<<<(B_ * H_) / 256, 256>>>(out + (size_t)B_ * S_ * O_);
}

// round 17
// speedup vs baseline: 1.3529x; 1.3529x over previous
#include <cuda_runtime.h>

// ---------------------------------------------------------------------------
// SimpleRNN: x[128,1024,256], W_i2h[512,768] (=[Wx|Wh]), b_i2h[512],
//            W_h2o[256,512], b_h2o[256]
// out = concat( outputs[128,1024,256], h_last[128,512] ), fp32
//
// Phase 1: xW GEMM.  Phase 2: persistent scan (round-13 structure: 128 CTAs =
// 16 jg x 8 bg) WITH the output GEMM fused into each step's latency window.
// ---------------------------------------------------------------------------

namespace {
constexpr int B_ = 128;   // batch
constexpr int S_ = 1024;  // seq
constexpr int I_ = 256;   // in
constexpr int H_ = 512;   // hid
constexpr int O_ = 256;   // out
constexpr int BG = 8;     // batch groups
constexpr int JG = 16;    // hid groups (CTAs per batch group)
constexpr int BSL = B_ / BG;  // 16 batch rows per group
}

// Scratch (allocation-free rule: __device__ globals)
__device__ float    g_xw[(size_t)S_ * B_ * H_];   // 256 MB, [t][b][h]
__device__ float    g_hs[(size_t)S_ * B_ * H_];   // 256 MB, [t][b][h]
__device__ unsigned g_flag[BG * S_ * JG];         // per-(bg,t,jg) done flags

// ---------------------------------------------------------------------------
__global__ void zero_flag_kernel() {
    int i = blockIdx.x * blockDim.x + threadIdx.x;
    if (i < BG * S_ * JG) g_flag[i] = 0u;
}

// ---------------------------------------------------------------------------
// C[r][c] = sum_k A'[r][k]*B[c][k] + bias[c].  128x128 tile, 8x8 micro-tile
// (split halves -> conflict-free LDS.128).  Row r: hi=r/D, lo=r%D;
// A row = (lo*SWAP + hi)*K.   [verified 69% fma]
template<int K, int N, int BSTR, int D, int SWAP>
__global__ void __launch_bounds__(256, 2) gemm_bias_kernel(
    const float* __restrict__ A, const float* __restrict__ Bm,
    const float* __restrict__ bias, float* __restrict__ C)
{
    __shared__ float As[16][132];
    __shared__ float Bs[16][132];
    const int tid = threadIdx.x;
    const int r0  = blockIdx.y * 128;
    const int c0  = blockIdx.x * 128;

    const int arow_l = tid >> 1;
    const int ak     = (tid & 1) * 8;
    const int r  = r0 + arow_l;
    const int hi = r / D, lo = r % D;
    const float* Arow = A + ((size_t)lo * SWAP + hi) * K + ak;
    const float* Brow = Bm + (size_t)(c0 + arow_l) * BSTR + ak;

    const int ty = tid >> 4, tx = tid & 15;
    float acc[2][4][2][4] = {};

    float4 a0 = *reinterpret_cast<const float4*>(Arow);
    float4 a1 = *reinterpret_cast<const float4*>(Arow + 4);
    float4 b0 = *reinterpret_cast<const float4*>(Brow);
    float4 b1 = *reinterpret_cast<const float4*>(Brow + 4);

    for (int kc = 0; kc < K; kc += 16) {
        __syncthreads();
        As[ak+0][arow_l]=a0.x; As[ak+1][arow_l]=a0.y; As[ak+2][arow_l]=a0.z; As[ak+3][arow_l]=a0.w;
        As[ak+4][arow_l]=a1.x; As[ak+5][arow_l]=a1.y; As[ak+6][arow_l]=a1.z; As[ak+7][arow_l]=a1.w;
        Bs[ak+0][arow_l]=b0.x; Bs[ak+1][arow_l]=b0.y; Bs[ak+2][arow_l]=b0.z; Bs[ak+3][arow_l]=b0.w;
        Bs[ak+4][arow_l]=b1.x; Bs[ak+5][arow_l]=b1.y; Bs[ak+6][arow_l]=b1.z; Bs[ak+7][arow_l]=b1.w;
        __syncthreads();
        if (kc + 16 < K) {
            a0 = *reinterpret_cast<const float4*>(Arow + kc + 16);
            a1 = *reinterpret_cast<const float4*>(Arow + kc + 16 + 4);
            b0 = *reinterpret_cast<const float4*>(Brow + kc + 16);
            b1 = *reinterpret_cast<const float4*>(Brow + kc + 16 + 4);
        }
#pragma unroll
        for (int kk = 0; kk < 16; ++kk) {
            float4 af0 = *reinterpret_cast<const float4*>(&As[kk][ty * 4]);
            float4 af1 = *reinterpret_cast<const float4*>(&As[kk][ty * 4 + 64]);
            float4 bf0 = *reinterpret_cast<const float4*>(&Bs[kk][tx * 4]);
            float4 bf1 = *reinterpret_cast<const float4*>(&Bs[kk][tx * 4 + 64]);
            float av[2][4] = {{af0.x,af0.y,af0.z,af0.w},{af1.x,af1.y,af1.z,af1.w}};
            float bv[2][4] = {{bf0.x,bf0.y,bf0.z,bf0.w},{bf1.x,bf1.y,bf1.z,bf1.w}};
#pragma unroll
            for (int ri = 0; ri < 2; ++ri)
#pragma unroll
                for (int i = 0; i < 4; ++i)
#pragma unroll
                    for (int ci = 0; ci < 2; ++ci)
#pragma unroll
                        for (int j = 0; j < 4; ++j)
                            acc[ri][i][ci][j] = fmaf(av[ri][i], bv[ci][j], acc[ri][i][ci][j]);
        }
    }

    float4 bsv0 = *reinterpret_cast<const float4*>(bias + c0 + tx * 4);
    float4 bsv1 = *reinterpret_cast<const float4*>(bias + c0 + 64 + tx * 4);
    float bb[2][4] = {{bsv0.x,bsv0.y,bsv0.z,bsv0.w},{bsv1.x,bsv1.y,bsv1.z,bsv1.w}};
#pragma unroll
    for (int ri = 0; ri < 2; ++ri)
#pragma unroll
        for (int i = 0; i < 4; ++i) {
            const size_t rowoff = (size_t)(r0 + ri * 64 + ty * 4 + i) * N;
#pragma unroll
            for (int ci = 0; ci < 2; ++ci) {
                float4 v;
                v.x = acc[ri][i][ci][0] + bb[ci][0];
                v.y = acc[ri][i][ci][1] + bb[ci][1];
                v.z = acc[ri][i][ci][2] + bb[ci][2];
                v.w = acc[ri][i][ci][3] + bb[ci][3];
                *reinterpret_cast<float4*>(C + rowoff + c0 + ci * 64 + tx * 4) = v;
            }
        }
}

// ---------------------------------------------------------------------------
// Multi-value butterfly on array AR: merge HALF*2 accs at xor-offset O.
#define RED_LEVEL_A(AR, O, HALF)                                             \
    {                                                                        \
        const bool up_ = (lane & (O)) != 0;                                  \
        _Pragma("unroll")                                                    \
        for (int q_ = 0; q_ < (HALF); ++q_) {                                \
            float s_ = up_ ? AR[q_] : AR[q_ + (HALF)];                       \
            float r_ = __shfl_xor_sync(0xffffffffu, s_, (O));                \
            AR[q_] = (up_ ? AR[q_ + (HALF)] : AR[q_]) + r_;                  \
        }                                                                    \
    }

// Persistent scan + fused output GEMM.  Grid (JG, BG) = (16, 8), 256 threads.
// CTA (jg,bg): hid slice [jg*32,+32), o slice [jg*16,+16), batch [bg*16,+16).
// Step t: acquire h_{t-1} -> stage 32KB -> h-GEMM (64 accs/lane, 62-shuffle
// merge) -> tanh -> release h_t -> THEN compute out[t-1] tile from the staged
// h_{t-1} still in smem (fills the next acquire's latency window).
__global__ void __launch_bounds__(256, 1) rnn_scan_kernel(
    const float* __restrict__ W, const float* __restrict__ Wo,
    const float* __restrict__ bo, float* __restrict__ out)
{
    const int jg    = blockIdx.x;   // 0..15
    const int bg    = blockIdx.y;   // 0..7
    const int tid   = threadIdx.x;
    const int warp  = tid >> 5;
    const int lane  = tid & 31;
    const int jbase = jg * 32 + warp * 4;

    __shared__ float hsm[BSL * H_];   // 32 KB: h_{t-1} for this batch group

    // Register-resident Wh slice: w4[jj][i] = Wh[jbase+jj][128*i + 4*lane ..+3]
    float4 w4[4][4];
#pragma unroll
    for (int jj = 0; jj < 4; ++jj)
#pragma unroll
        for (int i = 0; i < 4; ++i)
            w4[jj][i] = *reinterpret_cast<const float4*>(
                W + (size_t)(jbase + jj) * (I_ + H_) + I_ + 128 * i + 4 * lane);

    // Register-resident Wo slice: 2 o-rows per warp
    const int obase = jg * 16 + warp * 2;
    float4 wo4[2][4];
#pragma unroll
    for (int oo = 0; oo < 2; ++oo)
#pragma unroll
        for (int i = 0; i < 4; ++i)
            wo4[oo][i] = *reinterpret_cast<const float4*>(
                Wo + (size_t)(obase + oo) * H_ + 128 * i + 4 * lane);

    unsigned* flg = g_flag + (size_t)bg * S_ * JG;
    const int ob  = lane >> 1;                 // batch row (h output)
    const int oj  = jbase + (lane & 1) * 2;    // 2 consecutive j's
    const int oo2 = obase + (lane & 1);        // out column this lane stores
    const float bo_v = bo[oo2];
    // out[b][s][o]: base for this lane's (b, o), s added per step
    float* outp = out + (size_t)(bg * BSL + (lane >> 1)) * S_ * O_ + oo2;

    for (int t = 0; t < S_; ++t) {
        float s0 = 0.f, s1 = 0.f;
        const size_t rowoff = ((size_t)t * B_ + bg * BSL + ob) * H_ + oj;
        float2 xv;

        if (t > 0) {
            // acquire: parallel poll of the 16 per-jg flags for step t-1
            if (warp == 0) {
                const unsigned* f = flg + (size_t)(t - 1) * JG + (lane & 15);
                unsigned v;
                do {
                    asm volatile("ld.relaxed.gpu.global.u32 %0, [%1];"
                                 : "=r"(v) : "l"(f) : "memory");
                } while (!__all_sync(0xffffffffu, v != 0u));
                asm volatile("fence.acq_rel.gpu;" ::: "memory");
            }
            __syncthreads();

            xv = *reinterpret_cast<const float2*>(g_xw + rowoff);  // early LDG
            {   // stage h_{t-1} (32 KB, 8 float4/thread, coalesced)
                const float4* src = reinterpret_cast<const float4*>(
                    g_hs + ((size_t)(t - 1) * B_ + bg * BSL) * H_);
                float4* dst = reinterpret_cast<float4*>(hsm);
#pragma unroll
                for (int i = 0; i < (BSL * H_ / 4) / 256; ++i)
                    dst[tid + 256 * i] = src[tid + 256 * i];
            }
            __syncthreads();

            float A[64];   // A[b*4+jj]
#pragma unroll
            for (int q = 0; q < 64; ++q) A[q] = 0.f;
#pragma unroll
            for (int i = 0; i < 4; ++i) {
                const int kofs = 4 * lane + 128 * i;
#pragma unroll
                for (int b = 0; b < 16; ++b) {
                    float4 hv = *reinterpret_cast<const float4*>(hsm + b * H_ + kofs);
#pragma unroll
                    for (int jj = 0; jj < 4; ++jj) {
                        float a = A[b * 4 + jj];
                        a = fmaf(hv.x, w4[jj][i].x, a);
                        a = fmaf(hv.y, w4[jj][i].y, a);
                        a = fmaf(hv.z, w4[jj][i].z, a);
                        a = fmaf(hv.w, w4[jj][i].w, a);
                        A[b * 4 + jj] = a;
                    }
                }
            }
            RED_LEVEL_A(A, 16, 32)
            RED_LEVEL_A(A, 8, 16)
            RED_LEVEL_A(A, 4, 8)
            RED_LEVEL_A(A, 2, 4)
            RED_LEVEL_A(A, 1, 2)
            s0 = A[0];
            s1 = A[1];
        } else {
            xv = *reinterpret_cast<const float2*>(g_xw + rowoff);
        }

        float2 hv2;
        hv2.x = tanhf(xv.x + s0);
        hv2.y = tanhf(xv.y + s1);
        *reinterpret_cast<float2*>(g_hs + rowoff) = hv2;

        __syncthreads();
        if (tid == 0) {   // release: publish our hid slice of h_t FIRST
            asm volatile("fence.acq_rel.gpu;" ::: "memory");
            asm volatile("st.relaxed.gpu.global.u32 [%0], %1;"
                         :: "l"(flg + (size_t)t * JG + jg), "r"(1u) : "memory");
        }

        if (t > 0) {
            // fused output GEMM for step t-1, from h_{t-1} still in smem.
            // (reads of hsm are ordered before next step's staging writes by
            // the __syncthreads after the next acquire)
            float Cq[32];   // Cq[b*2+oo]
#pragma unroll
            for (int q = 0; q < 32; ++q) Cq[q] = 0.f;
#pragma unroll
            for (int i = 0; i < 4; ++i) {
                const int kofs = 4 * lane + 128 * i;
#pragma unroll
                for (int b = 0; b < 16; ++b) {
                    float4 hv = *reinterpret_cast<const float4*>(hsm + b * H_ + kofs);
#pragma unroll
                    for (int oo = 0; oo < 2; ++oo) {
                        float a = Cq[b * 2 + oo];
                        a = fmaf(hv.x, wo4[oo][i].x, a);
                        a = fmaf(hv.y, wo4[oo][i].y, a);
                        a = fmaf(hv.z, wo4[oo][i].z, a);
                        a = fmaf(hv.w, wo4[oo][i].w, a);
                        Cq[b * 2 + oo] = a;
                    }
                }
            }
            RED_LEVEL_A(Cq, 16, 16)
            RED_LEVEL_A(Cq, 8, 8)
            RED_LEVEL_A(Cq, 4, 4)
            RED_LEVEL_A(Cq, 2, 2)
            RED_LEVEL_A(Cq, 1, 1)
            outp[(size_t)(t - 1) * O_] = Cq[0] + bo_v;   // lane -> (b=lane>>1, oo2)
        }
    }

    // tail: out[S-1] — acquire h_{S-1}, stage, compute
    if (warp == 0) {
        const unsigned* f = flg + (size_t)(S_ - 1) * JG + (lane & 15);
        unsigned v;
        do {
            asm volatile("ld.relaxed.gpu.global.u32 %0, [%1];"
                         : "=r"(v) : "l"(f) : "memory");
        } while (!__all_sync(0xffffffffu, v != 0u));
        asm volatile("fence.acq_rel.gpu;" ::: "memory");
    }
    __syncthreads();
    {
        const float4* src = reinterpret_cast<const float4*>(
            g_hs + ((size_t)(S_ - 1) * B_ + bg * BSL) * H_);
        float4* dst = reinterpret_cast<float4*>(hsm);
#pragma unroll
        for (int i = 0; i < (BSL * H_ / 4) / 256; ++i)
            dst[tid + 256 * i] = src[tid + 256 * i];
    }
    __syncthreads();
    {
        float Cq[32];
#pragma unroll
        for (int q = 0; q < 32; ++q) Cq[q] = 0.f;
#pragma unroll
        for (int i = 0; i < 4; ++i) {
            const int kofs = 4 * lane + 128 * i;
#pragma unroll
            for (int b = 0; b < 16; ++b) {
                float4 hv = *reinterpret_cast<const float4*>(hsm + b * H_ + kofs);
#pragma unroll
                for (int oo = 0; oo < 2; ++oo) {
                    float a = Cq[b * 2 + oo];
                    a = fmaf(hv.x, wo4[oo][i].x, a);
                    a = fmaf(hv.y, wo4[oo][i].y, a);
                    a = fmaf(hv.z, wo4[oo][i].z, a);
                    a = fmaf(hv.w, wo4[oo][i].w, a);
                    Cq[b * 2 + oo] = a;
                }
            }
        }
        RED_LEVEL_A(Cq, 16, 16)
        RED_LEVEL_A(Cq, 8, 8)
        RED_LEVEL_A(Cq, 4, 4)
        RED_LEVEL_A(Cq, 2, 2)
        RED_LEVEL_A(Cq, 1, 1)
        outp[(size_t)(S_ - 1) * O_] = Cq[0] + bo_v;
    }
}

// ---------------------------------------------------------------------------
__global__ void copy_hlast_kernel(float* __restrict__ out) {
    int i = blockIdx.x * blockDim.x + threadIdx.x;
    out[i] = g_hs[(size_t)(S_ - 1) * B_ * H_ + i];   // [b][h] slice, contiguous
}

// ---------------------------------------------------------------------------
extern "C" void kernel_launch(void* const* d_in, const int* in_sizes, int n_in,
                              void* d_out, int out_size)
{
    const float* x  = (const float*)d_in[0];   // [128,1024,256]
    const float* Wi = (const float*)d_in[1];   // [512,768]
    const float* bi = (const float*)d_in[2];   // [512]
    const float* Wo = (const float*)d_in[3];   // [256,512]
    const float* bo = (const float*)d_in[4];   // [256]
    float* out = (float*)d_out;

    float* xw_d = nullptr;
    cudaGetSymbolAddress((void**)&xw_d, g_xw);

    // reset sync flags (graph replays must be deterministic)
    zero_flag_kernel<<<(BG * S_ * JG + 255) / 256, 256>>>();

    // Phase 1: xW[t][b][h]  (r = t*128+b, A row = (b*S_+t)*I_)
    {
        dim3 g(H_ / 128, (S_ * B_) / 128);
        gemm_bias_kernel<I_, H_, I_ + H_, B_, S_><<<g, 256>>>(x, Wi, bi, xw_d);
    }

    // Phase 2+3 fused: scan + output GEMM (persistent, 128 co-resident CTAs)
    rnn_scan_kernel<<<dim3(JG, BG), 256>>>(Wi, Wo, bo, out);

    // h_last
    if (out_size >= B_ * S_ * O_ + B_ * H_)
        copy_hlast_kernel<<<(B_ * H_) / 256, 256>>>(out + (size_t)B_ * S_ * O_);
}